// round 1
// baseline (speedup 1.0000x reference)
#include <cuda_runtime.h>
#include <cuda_bf16.h>
#include <math.h>

// Problem constants
#define CC      512
#define NHEADS  8
#define HDIM    64
#define BATCH   4
#define SEQ     2304            // 48*48
#define SCALE   0.125f          // 1/sqrt(64)

// Scratch (device globals — no runtime allocation allowed)
__device__ float g_qkv[(size_t)BATCH * 3 * CC * SEQ];   // [b][o][s], o in [0,1536)
__device__ float g_att[(size_t)BATCH * CC * SEQ];       // [b][c][s]

// ---------------------------------------------------------------------------
// SGEMM + bias:  C[b][m][n] = sum_k A[m][k] * B[b][k][n] + bias[m]
// A row-major MxK (shared across batch), B row-major KxN per batch.
// Tiles: BM=BN=64, BK=16, 256 threads, 4x4 per thread.
// ---------------------------------------------------------------------------
#define BM 64
#define BN 64
#define BK 16

__global__ __launch_bounds__(256)
void sgemm_bias(const float* __restrict__ A, const float* __restrict__ B,
                const float* __restrict__ bias, float* __restrict__ C,
                int M, int N, int K, long strideB, long strideC)
{
    __shared__ float As[BK][BM + 1];
    __shared__ float Bs[BK][BN];

    const int bz = blockIdx.z;
    const float* Bb = B + (long)bz * strideB;
    float*       Cb = C + (long)bz * strideC;

    const int tid = threadIdx.x;
    const int tx = tid & 15;        // n-group
    const int ty = tid >> 4;        // m-group
    const int row0 = blockIdx.y * BM;
    const int col0 = blockIdx.x * BN;

    float acc[4][4];
#pragma unroll
    for (int i = 0; i < 4; i++)
#pragma unroll
        for (int j = 0; j < 4; j++) acc[i][j] = 0.0f;

    for (int k0 = 0; k0 < K; k0 += BK) {
        // Load A tile (BM x BK) -> As[k][m]
        {
            const int c = tid & 15;       // k
            const int r = tid >> 4;       // m (16 rows, x4)
#pragma unroll
            for (int i = 0; i < 4; i++)
                As[c][r + i * 16] = A[(long)(row0 + r + i * 16) * K + k0 + c];
        }
        // Load B tile (BK x BN) -> Bs[k][n]
        {
            const int s = tid & 63;
            const int kk = tid >> 6;      // 0..3, x4
#pragma unroll
            for (int i = 0; i < 4; i++)
                Bs[kk + i * 4][s] = Bb[(long)(k0 + kk + i * 4) * N + col0 + s];
        }
        __syncthreads();

#pragma unroll
        for (int k = 0; k < BK; k++) {
            float a[4], b[4];
#pragma unroll
            for (int i = 0; i < 4; i++) a[i] = As[k][ty * 4 + i];
#pragma unroll
            for (int j = 0; j < 4; j++) b[j] = Bs[k][tx * 4 + j];
#pragma unroll
            for (int i = 0; i < 4; i++)
#pragma unroll
                for (int j = 0; j < 4; j++) acc[i][j] = fmaf(a[i], b[j], acc[i][j]);
        }
        __syncthreads();
    }

#pragma unroll
    for (int i = 0; i < 4; i++) {
        const float bv = bias[row0 + ty * 4 + i];
#pragma unroll
        for (int j = 0; j < 4; j++)
            Cb[(long)(row0 + ty * 4 + i) * N + col0 + tx * 4 + j] = acc[i][j] + bv;
    }
}

// ---------------------------------------------------------------------------
// Flash attention, fp32. qkv layout [b][o][s] with q:o=h*64+d, k:o=512+h*64+d,
// v:o=1024+h*64+d. Output [b][h*64+d][s].
// Block: 64 query rows; loop over 64-wide key tiles; online softmax.
// Thread map (256 thr): tx=tid&15, ty=tid>>4; logits: rows ty*4.., cols tx*4..;
// PV: rows ty*4.., dims tx*4.. The 16 lanes with equal ty are contiguous in a
// warp -> width-16 shuffles for row max/sum.
// ---------------------------------------------------------------------------
#define QT 64
#define KT 64
#define KSTRIDE 65          // pad to avoid 16-way conflicts on d-major reads
// dyn smem floats: Qs 64*64, Ks 64*65, Vs 64*65, P 64*64
#define ATT_SMEM_FLOATS (QT*QT + HDIM*KSTRIDE + HDIM*KSTRIDE + QT*KT)
#define ATT_SMEM_BYTES  (ATT_SMEM_FLOATS * 4)

__global__ __launch_bounds__(256)
void attn_kernel(const float* __restrict__ qkv, float* __restrict__ out)
{
    extern __shared__ float sm[];
    float* Qs = sm;                         // [d][i]  stride QT
    float* Ks = Qs + QT * QT;               // [d][j]  stride KSTRIDE
    float* Vs = Ks + HDIM * KSTRIDE;        // [d][j]  stride KSTRIDE
    float* P  = Vs + HDIM * KSTRIDE;        // [i][j]  stride KT

    const int b = blockIdx.z, h = blockIdx.y;
    const int s0 = blockIdx.x * QT;
    const int tid = threadIdx.x;
    const int tx = tid & 15;
    const int ty = tid >> 4;

    const long bo = (long)b * 3 * CC * SEQ;
    const float* qg = qkv + bo + (long)(h * HDIM) * SEQ + s0;
    const float* kg = qkv + bo + (long)(CC + h * HDIM) * SEQ;
    const float* vg = qkv + bo + (long)(2 * CC + h * HDIM) * SEQ;

    // Load Q tile: Qs[d][i] = q[d][s0+i]
    {
        const int c = tid & 63;
        const int r = tid >> 6;     // 0..3
#pragma unroll
        for (int i = 0; i < 16; i++)
            Qs[(r + i * 4) * QT + c] = qg[(long)(r + i * 4) * SEQ + c];
    }

    float m[4], l[4], O[4][4];
#pragma unroll
    for (int i = 0; i < 4; i++) {
        m[i] = -1e30f; l[i] = 0.0f;
#pragma unroll
        for (int j = 0; j < 4; j++) O[i][j] = 0.0f;
    }

    for (int t0 = 0; t0 < SEQ; t0 += KT) {
        __syncthreads();   // protect K/V/P from previous iteration
        // Load K,V tiles
        {
            const int c = tid & 63;
            const int r = tid >> 6;
#pragma unroll
            for (int i = 0; i < 16; i++) {
                const int d = r + i * 4;
                Ks[d * KSTRIDE + c] = kg[(long)d * SEQ + t0 + c];
                Vs[d * KSTRIDE + c] = vg[(long)d * SEQ + t0 + c];
            }
        }
        __syncthreads();

        // Logits: acc[i][j] = sum_d Q[d][i]*K[d][j]
        float acc[4][4];
#pragma unroll
        for (int i = 0; i < 4; i++)
#pragma unroll
            for (int j = 0; j < 4; j++) acc[i][j] = 0.0f;

#pragma unroll 8
        for (int d = 0; d < HDIM; d++) {
            float a[4], kk[4];
#pragma unroll
            for (int i = 0; i < 4; i++) a[i]  = Qs[d * QT + ty * 4 + i];
#pragma unroll
            for (int j = 0; j < 4; j++) kk[j] = Ks[d * KSTRIDE + tx * 4 + j];
#pragma unroll
            for (int i = 0; i < 4; i++)
#pragma unroll
                for (int j = 0; j < 4; j++) acc[i][j] = fmaf(a[i], kk[j], acc[i][j]);
        }

        // Row max (across the 16 lanes sharing ty)
        float rmax[4];
#pragma unroll
        for (int i = 0; i < 4; i++) {
            float v = acc[i][0] * SCALE;
#pragma unroll
            for (int j = 1; j < 4; j++) v = fmaxf(v, acc[i][j] * SCALE);
            rmax[i] = v;
        }
#pragma unroll
        for (int off = 8; off > 0; off >>= 1)
#pragma unroll
            for (int i = 0; i < 4; i++)
                rmax[i] = fmaxf(rmax[i], __shfl_xor_sync(0xffffffffu, rmax[i], off, 16));

        // Online softmax update
        float alpha[4], rsum[4];
#pragma unroll
        for (int i = 0; i < 4; i++) {
            const float mn = fmaxf(m[i], rmax[i]);
            alpha[i] = __expf(m[i] - mn);
            m[i] = mn;
            rsum[i] = 0.0f;
        }
#pragma unroll
        for (int i = 0; i < 4; i++)
#pragma unroll
            for (int j = 0; j < 4; j++) {
                const float p = __expf(acc[i][j] * SCALE - m[i]);
                P[(ty * 4 + i) * KT + tx * 4 + j] = p;
                rsum[i] += p;
            }
#pragma unroll
        for (int off = 8; off > 0; off >>= 1)
#pragma unroll
            for (int i = 0; i < 4; i++)
                rsum[i] += __shfl_xor_sync(0xffffffffu, rsum[i], off, 16);
#pragma unroll
        for (int i = 0; i < 4; i++) l[i] = l[i] * alpha[i] + rsum[i];

        // Rescale accumulators
#pragma unroll
        for (int i = 0; i < 4; i++)
#pragma unroll
            for (int j = 0; j < 4; j++) O[i][j] *= alpha[i];

        __syncthreads();   // P visible to all

        // O[i][d'=tx*4+j] += sum_j2 P[i][j2] * V[d'][j2]
#pragma unroll 8
        for (int j2 = 0; j2 < KT; j2++) {
            float p4[4], v4[4];
#pragma unroll
            for (int i = 0; i < 4; i++) p4[i] = P[(ty * 4 + i) * KT + j2];
#pragma unroll
            for (int j = 0; j < 4; j++) v4[j] = Vs[(tx * 4 + j) * KSTRIDE + j2];
#pragma unroll
            for (int i = 0; i < 4; i++)
#pragma unroll
                for (int j = 0; j < 4; j++) O[i][j] = fmaf(p4[i], v4[j], O[i][j]);
        }
    }

    // Write: out[b][h*64 + d][s0 + i] = O / l
    float* og = out + (long)b * CC * SEQ + (long)(h * HDIM) * SEQ + s0;
#pragma unroll
    for (int i = 0; i < 4; i++) {
        const float inv = 1.0f / l[i];
#pragma unroll
        for (int j = 0; j < 4; j++)
            og[(long)(tx * 4 + j) * SEQ + ty * 4 + i] = O[i][j] * inv;
    }
}

// ---------------------------------------------------------------------------
extern "C" void kernel_launch(void* const* d_in, const int* in_sizes, int n_in,
                              void* d_out, int out_size)
{
    const float* x    = (const float*)d_in[0];   // [B, C, H, W]
    const float* Wqkv = (const float*)d_in[1];   // [3C, C]
    const float* bqkv = (const float*)d_in[2];   // [3C]
    const float* Wout = (const float*)d_in[3];   // [C, C]
    const float* bout = (const float*)d_in[4];   // [C]
    float* out = (float*)d_out;                  // [B, C, H, W]

    float *qkvbuf = nullptr, *attbuf = nullptr;
    cudaGetSymbolAddress((void**)&qkvbuf, g_qkv);
    cudaGetSymbolAddress((void**)&attbuf, g_att);

    cudaFuncSetAttribute(attn_kernel,
                         cudaFuncAttributeMaxDynamicSharedMemorySize,
                         ATT_SMEM_BYTES);

    // 1) QKV projection: [1536x512] @ [512x2304] per batch
    {
        dim3 grid(SEQ / BN, (3 * CC) / BM, BATCH);
        sgemm_bias<<<grid, 256>>>(Wqkv, x, bqkv, qkvbuf,
                                  3 * CC, SEQ, CC,
                                  (long)CC * SEQ, (long)3 * CC * SEQ);
    }

    // 2) Attention per (b, h)
    {
        dim3 grid(SEQ / QT, NHEADS, BATCH);
        attn_kernel<<<grid, 256, ATT_SMEM_BYTES>>>(qkvbuf, attbuf);
    }

    // 3) Output projection: [512x512] @ [512x2304] per batch
    {
        dim3 grid(SEQ / BN, CC / BM, BATCH);
        sgemm_bias<<<grid, 256>>>(Wout, attbuf, bout, out,
                                  CC, SEQ, CC,
                                  (long)CC * SEQ, (long)CC * SEQ);
    }
}

// round 4
// speedup vs baseline: 2.2109x; 2.2109x over previous
#include <cuda_runtime.h>
#include <math.h>

#define CC      512
#define NHEADS  8
#define HDIM    64
#define BATCH   4
#define SEQ     2304
#define SCALE   0.125f

__device__ float g_qkv[(size_t)BATCH * 3 * CC * SEQ];   // [b][o][s]
__device__ float g_att[(size_t)BATCH * CC * SEQ];       // [b][c][s]

__device__ __forceinline__ unsigned f2tf(float x) {
    unsigned r;
    asm("cvt.rna.tf32.f32 %0, %1;" : "=r"(r) : "f"(x));
    return r;
}

__device__ __forceinline__ void mma_tf32(float* d,
                                         unsigned a0, unsigned a1, unsigned a2, unsigned a3,
                                         unsigned b0, unsigned b1) {
    asm("mma.sync.aligned.m16n8k8.row.col.f32.tf32.tf32.f32 "
        "{%0,%1,%2,%3}, {%4,%5,%6,%7}, {%8,%9}, {%0,%1,%2,%3};"
        : "+f"(d[0]), "+f"(d[1]), "+f"(d[2]), "+f"(d[3])
        : "r"(a0), "r"(a1), "r"(a2), "r"(a3), "r"(b0), "r"(b1));
}

// ---------------------------------------------------------------------------
// TF32 GEMM + bias: C[b][m][n] = sum_k A[m][k]*B[b][k][n] + bias[m]
// Block 128x128, BK=16, 256 threads (8 warps: 4 along M x 2 along N).
// ---------------------------------------------------------------------------
#define G_BM 128
#define G_BN 128
#define G_BK 16
#define AS_STRIDE 20
#define BS_STRIDE 136

__global__ __launch_bounds__(256, 2)
void gemm_tf32_bias(const float* __restrict__ A, const float* __restrict__ B,
                    const float* __restrict__ bias, float* __restrict__ C,
                    int M, int N, int K, long strideB, long strideC)
{
    __shared__ unsigned As[G_BM * AS_STRIDE];
    __shared__ unsigned Bs[G_BK * BS_STRIDE];

    const int bz = blockIdx.z;
    const float* Bb = B + (long)bz * strideB;
    float*       Cb = C + (long)bz * strideC;

    const int tid  = threadIdx.x;
    const int lane = tid & 31;
    const int wid  = tid >> 5;
    const int wm   = wid & 3;
    const int wn   = wid >> 2;
    const int lr   = lane >> 2;
    const int lc   = lane & 3;

    const int row0 = blockIdx.y * G_BM;
    const int col0 = blockIdx.x * G_BN;

    float acc[2][8][4];
#pragma unroll
    for (int mt = 0; mt < 2; mt++)
#pragma unroll
        for (int nt = 0; nt < 8; nt++)
#pragma unroll
            for (int i = 0; i < 4; i++) acc[mt][nt][i] = 0.0f;

    const int ar = tid >> 1;
    const int ac = (tid & 1) * 8;
    const int br = tid >> 4;
    const int bc = (tid & 15) * 8;

    for (int k0 = 0; k0 < K; k0 += G_BK) {
        {
            const float4 v0 = *(const float4*)&A[(long)(row0 + ar) * K + k0 + ac];
            const float4 v1 = *(const float4*)&A[(long)(row0 + ar) * K + k0 + ac + 4];
            unsigned* p = &As[ar * AS_STRIDE + ac];
            p[0] = f2tf(v0.x); p[1] = f2tf(v0.y); p[2] = f2tf(v0.z); p[3] = f2tf(v0.w);
            p[4] = f2tf(v1.x); p[5] = f2tf(v1.y); p[6] = f2tf(v1.z); p[7] = f2tf(v1.w);
        }
        {
            const float4 v0 = *(const float4*)&Bb[(long)(k0 + br) * N + col0 + bc];
            const float4 v1 = *(const float4*)&Bb[(long)(k0 + br) * N + col0 + bc + 4];
            unsigned* p = &Bs[br * BS_STRIDE + bc];
            p[0] = f2tf(v0.x); p[1] = f2tf(v0.y); p[2] = f2tf(v0.z); p[3] = f2tf(v0.w);
            p[4] = f2tf(v1.x); p[5] = f2tf(v1.y); p[6] = f2tf(v1.z); p[7] = f2tf(v1.w);
        }
        __syncthreads();

#pragma unroll
        for (int kk = 0; kk < 2; kk++) {
            unsigned a[2][4];
#pragma unroll
            for (int mt = 0; mt < 2; mt++) {
                const int mrow = wm * 32 + mt * 16 + lr;
                a[mt][0] = As[(mrow)     * AS_STRIDE + kk * 8 + lc];
                a[mt][1] = As[(mrow + 8) * AS_STRIDE + kk * 8 + lc];
                a[mt][2] = As[(mrow)     * AS_STRIDE + kk * 8 + lc + 4];
                a[mt][3] = As[(mrow + 8) * AS_STRIDE + kk * 8 + lc + 4];
            }
#pragma unroll
            for (int nt = 0; nt < 8; nt++) {
                const int ncol = wn * 64 + nt * 8 + lr;
                const unsigned b0 = Bs[(kk * 8 + lc)     * BS_STRIDE + ncol];
                const unsigned b1 = Bs[(kk * 8 + lc + 4) * BS_STRIDE + ncol];
#pragma unroll
                for (int mt = 0; mt < 2; mt++)
                    mma_tf32(acc[mt][nt], a[mt][0], a[mt][1], a[mt][2], a[mt][3], b0, b1);
            }
        }
        __syncthreads();
    }

#pragma unroll
    for (int mt = 0; mt < 2; mt++) {
        const int r0 = row0 + wm * 32 + mt * 16 + lr;
        const float bv0 = bias[r0];
        const float bv1 = bias[r0 + 8];
#pragma unroll
        for (int nt = 0; nt < 8; nt++) {
            const int c = col0 + wn * 64 + nt * 8 + 2 * lc;
            float2 s0 = make_float2(acc[mt][nt][0] + bv0, acc[mt][nt][1] + bv0);
            float2 s1 = make_float2(acc[mt][nt][2] + bv1, acc[mt][nt][3] + bv1);
            *(float2*)&Cb[(long)r0 * N + c]       = s0;
            *(float2*)&Cb[(long)(r0 + 8) * N + c] = s1;
        }
    }
}

// ---------------------------------------------------------------------------
// Flash attention, TF32 tensor cores.
// 128 queries/block, 8 warps (16 q each), 64-key tiles, online softmax.
// Q staged through smem ONCE then held in registers; the same smem bytes are
// then reused for the K/V tiles (lifetimes ordered by __syncthreads).
// ---------------------------------------------------------------------------
#define QT 128
#define KT 64
#define KS_STRIDE 72
#define VT_STRIDE 66
#define KS_UINTS (HDIM * KS_STRIDE)                 // 4608
#define KV_UINTS (KS_UINTS + KT * VT_STRIDE)        // 8832 (35.3 KB)
#define QX_UINTS (QT * HDIM)                        // 8192 (32 KB)
#define SM_UINTS (KV_UINTS > QX_UINTS ? KV_UINTS : QX_UINTS)

__global__ __launch_bounds__(256, 2)
void attn_tf32(const float* __restrict__ qkv, float* __restrict__ out)
{
    __shared__ __align__(16) unsigned smem_raw[SM_UINTS];
    float*    Qx = (float*)smem_raw;            // [q][d], one-shot staging
    unsigned* Ks = smem_raw;                    // [d][key]
    unsigned* Vt = smem_raw + KS_UINTS;         // [key][d]

    const int b = blockIdx.z, h = blockIdx.y;
    const int s0 = blockIdx.x * QT;
    const int tid  = threadIdx.x;
    const int lane = tid & 31;
    const int wid  = tid >> 5;
    const int lr   = lane >> 2;
    const int lc   = lane & 3;
    const int q0   = wid * 16;

    const long bo = (long)b * 3 * CC * SEQ;
    const float* qg = qkv + bo + (long)(h * HDIM) * SEQ + s0;
    const float* kg = qkv + bo + (long)(CC + h * HDIM) * SEQ;
    const float* vg = qkv + bo + (long)(2 * CC + h * HDIM) * SEQ;

    // Stage Q transposed into smem, then lift this warp's fragments to regs.
    {
        const int d  = tid >> 2;
        const int qb = (tid & 3) * 32;
#pragma unroll
        for (int j = 0; j < 32; j += 4) {
            const float4 v = *(const float4*)&qg[(long)d * SEQ + qb + j];
            Qx[(qb + j)     * HDIM + d] = v.x;
            Qx[(qb + j + 1) * HDIM + d] = v.y;
            Qx[(qb + j + 2) * HDIM + d] = v.z;
            Qx[(qb + j + 3) * HDIM + d] = v.w;
        }
    }
    __syncthreads();

    unsigned qf[8][4];
#pragma unroll
    for (int kk = 0; kk < 8; kk++) {
        qf[kk][0] = f2tf(Qx[(q0 + lr)     * HDIM + kk * 8 + lc]);
        qf[kk][1] = f2tf(Qx[(q0 + 8 + lr) * HDIM + kk * 8 + lc]);
        qf[kk][2] = f2tf(Qx[(q0 + lr)     * HDIM + kk * 8 + lc + 4]);
        qf[kk][3] = f2tf(Qx[(q0 + 8 + lr) * HDIM + kk * 8 + lc + 4]);
    }

    float m0 = -1e30f, m1 = -1e30f, l0 = 0.0f, l1 = 0.0f;
    float O[8][4];
#pragma unroll
    for (int nt = 0; nt < 8; nt++)
#pragma unroll
        for (int i = 0; i < 4; i++) O[nt][i] = 0.0f;

    const int kvd = tid >> 2;
    const int kvs = (tid & 3) * 16;

    for (int t0 = 0; t0 < SEQ; t0 += KT) {
        __syncthreads();   // orders prior reads (incl. Qx/qf) before overwrite
#pragma unroll
        for (int j = 0; j < 16; j += 4) {
            const float4 kv = *(const float4*)&kg[(long)kvd * SEQ + t0 + kvs + j];
            const float4 vv = *(const float4*)&vg[(long)kvd * SEQ + t0 + kvs + j];
            unsigned* kp = &Ks[kvd * KS_STRIDE + kvs + j];
            kp[0] = f2tf(kv.x); kp[1] = f2tf(kv.y); kp[2] = f2tf(kv.z); kp[3] = f2tf(kv.w);
            Vt[(kvs + j)     * VT_STRIDE + kvd] = f2tf(vv.x);
            Vt[(kvs + j + 1) * VT_STRIDE + kvd] = f2tf(vv.y);
            Vt[(kvs + j + 2) * VT_STRIDE + kvd] = f2tf(vv.z);
            Vt[(kvs + j + 3) * VT_STRIDE + kvd] = f2tf(vv.w);
        }
        __syncthreads();

        float acc[8][4];
#pragma unroll
        for (int nt = 0; nt < 8; nt++)
#pragma unroll
            for (int i = 0; i < 4; i++) acc[nt][i] = 0.0f;

#pragma unroll
        for (int kk = 0; kk < 8; kk++) {
#pragma unroll
            for (int nt = 0; nt < 8; nt++) {
                const unsigned b0 = Ks[(kk * 8 + lc)     * KS_STRIDE + nt * 8 + lr];
                const unsigned b1 = Ks[(kk * 8 + lc + 4) * KS_STRIDE + nt * 8 + lr];
                mma_tf32(acc[nt], qf[kk][0], qf[kk][1], qf[kk][2], qf[kk][3], b0, b1);
            }
        }

        // Online softmax
        float rmax0 = -1e30f, rmax1 = -1e30f;
#pragma unroll
        for (int nt = 0; nt < 8; nt++) {
            rmax0 = fmaxf(rmax0, fmaxf(acc[nt][0], acc[nt][1]));
            rmax1 = fmaxf(rmax1, fmaxf(acc[nt][2], acc[nt][3]));
        }
        rmax0 *= SCALE; rmax1 *= SCALE;
#pragma unroll
        for (int off = 1; off <= 2; off <<= 1) {
            rmax0 = fmaxf(rmax0, __shfl_xor_sync(0xffffffffu, rmax0, off));
            rmax1 = fmaxf(rmax1, __shfl_xor_sync(0xffffffffu, rmax1, off));
        }
        const float mn0 = fmaxf(m0, rmax0), mn1 = fmaxf(m1, rmax1);
        const float al0 = __expf(m0 - mn0), al1 = __expf(m1 - mn1);
        m0 = mn0; m1 = mn1;

        float rs0 = 0.0f, rs1 = 0.0f;
#pragma unroll
        for (int nt = 0; nt < 8; nt++) {
            acc[nt][0] = __expf(acc[nt][0] * SCALE - m0); rs0 += acc[nt][0];
            acc[nt][1] = __expf(acc[nt][1] * SCALE - m0); rs0 += acc[nt][1];
            acc[nt][2] = __expf(acc[nt][2] * SCALE - m1); rs1 += acc[nt][2];
            acc[nt][3] = __expf(acc[nt][3] * SCALE - m1); rs1 += acc[nt][3];
        }
#pragma unroll
        for (int off = 1; off <= 2; off <<= 1) {
            rs0 += __shfl_xor_sync(0xffffffffu, rs0, off);
            rs1 += __shfl_xor_sync(0xffffffffu, rs1, off);
        }
        l0 = l0 * al0 + rs0;
        l1 = l1 * al1 + rs1;

#pragma unroll
        for (int nt = 0; nt < 8; nt++) {
            O[nt][0] *= al0; O[nt][1] *= al0;
            O[nt][2] *= al1; O[nt][3] *= al1;
        }

        // P.V : accum-layout -> A-fragment via quad shuffles
        const int sL1 = (lane & ~3) | (lc >> 1);
        const int sL2 = sL1 + 2;
        const bool odd = (lc & 1);
#pragma unroll
        for (int kc = 0; kc < 8; kc++) {
            const float q00 = __shfl_sync(0xffffffffu, acc[kc][0], sL1);
            const float q01 = __shfl_sync(0xffffffffu, acc[kc][1], sL1);
            const float q10 = __shfl_sync(0xffffffffu, acc[kc][2], sL1);
            const float q11 = __shfl_sync(0xffffffffu, acc[kc][3], sL1);
            const float r00 = __shfl_sync(0xffffffffu, acc[kc][0], sL2);
            const float r01 = __shfl_sync(0xffffffffu, acc[kc][1], sL2);
            const float r10 = __shfl_sync(0xffffffffu, acc[kc][2], sL2);
            const float r11 = __shfl_sync(0xffffffffu, acc[kc][3], sL2);
            const unsigned a0 = f2tf(odd ? q01 : q00);
            const unsigned a1 = f2tf(odd ? q11 : q10);
            const unsigned a2 = f2tf(odd ? r01 : r00);
            const unsigned a3 = f2tf(odd ? r11 : r10);
#pragma unroll
            for (int nt = 0; nt < 8; nt++) {
                const unsigned b0 = Vt[(kc * 8 + lc)     * VT_STRIDE + nt * 8 + lr];
                const unsigned b1 = Vt[(kc * 8 + lc + 4) * VT_STRIDE + nt * 8 + lr];
                mma_tf32(O[nt], a0, a1, a2, a3, b0, b1);
            }
        }
    }

    // Write out[b][h*64+d][s] = O / l
    float* og = out + (long)b * CC * SEQ + (long)(h * HDIM) * SEQ;
    const float inv0 = 1.0f / l0, inv1 = 1.0f / l1;
    const int s = s0 + q0 + lr;
#pragma unroll
    for (int nt = 0; nt < 8; nt++) {
        const int d0 = nt * 8 + 2 * lc;
        og[(long)d0 * SEQ + s]           = O[nt][0] * inv0;
        og[(long)(d0 + 1) * SEQ + s]     = O[nt][1] * inv0;
        og[(long)d0 * SEQ + s + 8]       = O[nt][2] * inv1;
        og[(long)(d0 + 1) * SEQ + s + 8] = O[nt][3] * inv1;
    }
}

// ---------------------------------------------------------------------------
extern "C" void kernel_launch(void* const* d_in, const int* in_sizes, int n_in,
                              void* d_out, int out_size)
{
    const float* x    = (const float*)d_in[0];
    const float* Wqkv = (const float*)d_in[1];
    const float* bqkv = (const float*)d_in[2];
    const float* Wout = (const float*)d_in[3];
    const float* bout = (const float*)d_in[4];
    float* out = (float*)d_out;

    float *qkvbuf = nullptr, *attbuf = nullptr;
    cudaGetSymbolAddress((void**)&qkvbuf, g_qkv);
    cudaGetSymbolAddress((void**)&attbuf, g_att);

    {
        dim3 grid(SEQ / G_BN, (3 * CC) / G_BM, BATCH);
        gemm_tf32_bias<<<grid, 256>>>(Wqkv, x, bqkv, qkvbuf,
                                      3 * CC, SEQ, CC,
                                      (long)CC * SEQ, (long)3 * CC * SEQ);
    }
    {
        dim3 grid(SEQ / QT, NHEADS, BATCH);
        attn_tf32<<<grid, 256>>>(qkvbuf, attbuf);
    }
    {
        dim3 grid(SEQ / G_BN, CC / G_BM, BATCH);
        gemm_tf32_bias<<<grid, 256>>>(Wout, attbuf, bout, out,
                                      CC, SEQ, CC,
                                      (long)CC * SEQ, (long)CC * SEQ);
    }
}

// round 5
// speedup vs baseline: 2.2115x; 1.0003x over previous
#include <cuda_runtime.h>
#include <math.h>

#define CC      512
#define NHEADS  8
#define HDIM    64
#define BATCH   4
#define SEQ     2304
#define SCALE   0.125f

__device__ float g_qkv[(size_t)BATCH * 3 * CC * SEQ];   // [b][o][s]
__device__ float g_att[(size_t)BATCH * CC * SEQ];       // [b][c][s]

__device__ __forceinline__ unsigned f2tf(float x) {
    unsigned r;
    asm("cvt.rna.tf32.f32 %0, %1;" : "=r"(r) : "f"(x));
    return r;
}

__device__ __forceinline__ void mma_tf32(float* d,
                                         unsigned a0, unsigned a1, unsigned a2, unsigned a3,
                                         unsigned b0, unsigned b1) {
    asm("mma.sync.aligned.m16n8k8.row.col.f32.tf32.tf32.f32 "
        "{%0,%1,%2,%3}, {%4,%5,%6,%7}, {%8,%9}, {%0,%1,%2,%3};"
        : "+f"(d[0]), "+f"(d[1]), "+f"(d[2]), "+f"(d[3])
        : "r"(a0), "r"(a1), "r"(a2), "r"(a3), "r"(b0), "r"(b1));
}

// ---------------------------------------------------------------------------
// TF32 GEMM + bias: C[b][m][n] = sum_k A[m][k]*B[b][k][n] + bias[m]
// Block 128x128, BK=16, 256 threads (8 warps: 4 along M x 2 along N).
// ---------------------------------------------------------------------------
#define G_BM 128
#define G_BN 128
#define G_BK 16
#define AS_STRIDE 20
#define BS_STRIDE 136

__global__ __launch_bounds__(256, 2)
void gemm_tf32_bias(const float* __restrict__ A, const float* __restrict__ B,
                    const float* __restrict__ bias, float* __restrict__ C,
                    int M, int N, int K, long strideB, long strideC)
{
    __shared__ unsigned As[G_BM * AS_STRIDE];
    __shared__ unsigned Bs[G_BK * BS_STRIDE];

    const int bz = blockIdx.z;
    const float* Bb = B + (long)bz * strideB;
    float*       Cb = C + (long)bz * strideC;

    const int tid  = threadIdx.x;
    const int lane = tid & 31;
    const int wid  = tid >> 5;
    const int wm   = wid & 3;
    const int wn   = wid >> 2;
    const int lr   = lane >> 2;
    const int lc   = lane & 3;

    const int row0 = blockIdx.y * G_BM;
    const int col0 = blockIdx.x * G_BN;

    float acc[2][8][4];
#pragma unroll
    for (int mt = 0; mt < 2; mt++)
#pragma unroll
        for (int nt = 0; nt < 8; nt++)
#pragma unroll
            for (int i = 0; i < 4; i++) acc[mt][nt][i] = 0.0f;

    const int ar = tid >> 1;
    const int ac = (tid & 1) * 8;
    const int br = tid >> 4;
    const int bc = (tid & 15) * 8;

    for (int k0 = 0; k0 < K; k0 += G_BK) {
        {
            const float4 v0 = *(const float4*)&A[(long)(row0 + ar) * K + k0 + ac];
            const float4 v1 = *(const float4*)&A[(long)(row0 + ar) * K + k0 + ac + 4];
            unsigned* p = &As[ar * AS_STRIDE + ac];
            p[0] = f2tf(v0.x); p[1] = f2tf(v0.y); p[2] = f2tf(v0.z); p[3] = f2tf(v0.w);
            p[4] = f2tf(v1.x); p[5] = f2tf(v1.y); p[6] = f2tf(v1.z); p[7] = f2tf(v1.w);
        }
        {
            const float4 v0 = *(const float4*)&Bb[(long)(k0 + br) * N + col0 + bc];
            const float4 v1 = *(const float4*)&Bb[(long)(k0 + br) * N + col0 + bc + 4];
            unsigned* p = &Bs[br * BS_STRIDE + bc];
            p[0] = f2tf(v0.x); p[1] = f2tf(v0.y); p[2] = f2tf(v0.z); p[3] = f2tf(v0.w);
            p[4] = f2tf(v1.x); p[5] = f2tf(v1.y); p[6] = f2tf(v1.z); p[7] = f2tf(v1.w);
        }
        __syncthreads();

#pragma unroll
        for (int kk = 0; kk < 2; kk++) {
            unsigned a[2][4];
#pragma unroll
            for (int mt = 0; mt < 2; mt++) {
                const int mrow = wm * 32 + mt * 16 + lr;
                a[mt][0] = As[(mrow)     * AS_STRIDE + kk * 8 + lc];
                a[mt][1] = As[(mrow + 8) * AS_STRIDE + kk * 8 + lc];
                a[mt][2] = As[(mrow)     * AS_STRIDE + kk * 8 + lc + 4];
                a[mt][3] = As[(mrow + 8) * AS_STRIDE + kk * 8 + lc + 4];
            }
#pragma unroll
            for (int nt = 0; nt < 8; nt++) {
                const int ncol = wn * 64 + nt * 8 + lr;
                const unsigned b0 = Bs[(kk * 8 + lc)     * BS_STRIDE + ncol];
                const unsigned b1 = Bs[(kk * 8 + lc + 4) * BS_STRIDE + ncol];
#pragma unroll
                for (int mt = 0; mt < 2; mt++)
                    mma_tf32(acc[mt][nt], a[mt][0], a[mt][1], a[mt][2], a[mt][3], b0, b1);
            }
        }
        __syncthreads();
    }

#pragma unroll
    for (int mt = 0; mt < 2; mt++) {
        const int r0 = row0 + wm * 32 + mt * 16 + lr;
        const float bv0 = bias[r0];
        const float bv1 = bias[r0 + 8];
#pragma unroll
        for (int nt = 0; nt < 8; nt++) {
            const int c = col0 + wn * 64 + nt * 8 + 2 * lc;
            float2 s0 = make_float2(acc[mt][nt][0] + bv0, acc[mt][nt][1] + bv0);
            float2 s1 = make_float2(acc[mt][nt][2] + bv1, acc[mt][nt][3] + bv1);
            *(float2*)&Cb[(long)r0 * N + c]       = s0;
            *(float2*)&Cb[(long)(r0 + 8) * N + c] = s1;
        }
    }
}

// ---------------------------------------------------------------------------
// Flash attention, TF32 tensor cores.
// 128 queries/block, 8 warps (16 q each), 64-key tiles, online softmax.
// Q staged through smem ONCE then held in registers; the same smem bytes are
// then reused for the K/V tiles (lifetimes ordered by __syncthreads).
// ---------------------------------------------------------------------------
#define QT 128
#define KT 64
#define KS_STRIDE 72
#define VT_STRIDE 66
#define KS_UINTS (HDIM * KS_STRIDE)                 // 4608
#define KV_UINTS (KS_UINTS + KT * VT_STRIDE)        // 8832 (35.3 KB)
#define QX_UINTS (QT * HDIM)                        // 8192 (32 KB)
#define SM_UINTS (KV_UINTS > QX_UINTS ? KV_UINTS : QX_UINTS)

__global__ __launch_bounds__(256, 2)
void attn_tf32(const float* __restrict__ qkv, float* __restrict__ out)
{
    __shared__ __align__(16) unsigned smem_raw[SM_UINTS];
    float*    Qx = (float*)smem_raw;            // [q][d], one-shot staging
    unsigned* Ks = smem_raw;                    // [d][key]
    unsigned* Vt = smem_raw + KS_UINTS;         // [key][d]

    const int b = blockIdx.z, h = blockIdx.y;
    const int s0 = blockIdx.x * QT;
    const int tid  = threadIdx.x;
    const int lane = tid & 31;
    const int wid  = tid >> 5;
    const int lr   = lane >> 2;
    const int lc   = lane & 3;
    const int q0   = wid * 16;

    const long bo = (long)b * 3 * CC * SEQ;
    const float* qg = qkv + bo + (long)(h * HDIM) * SEQ + s0;
    const float* kg = qkv + bo + (long)(CC + h * HDIM) * SEQ;
    const float* vg = qkv + bo + (long)(2 * CC + h * HDIM) * SEQ;

    // Stage Q transposed into smem, then lift this warp's fragments to regs.
    {
        const int d  = tid >> 2;
        const int qb = (tid & 3) * 32;
#pragma unroll
        for (int j = 0; j < 32; j += 4) {
            const float4 v = *(const float4*)&qg[(long)d * SEQ + qb + j];
            Qx[(qb + j)     * HDIM + d] = v.x;
            Qx[(qb + j + 1) * HDIM + d] = v.y;
            Qx[(qb + j + 2) * HDIM + d] = v.z;
            Qx[(qb + j + 3) * HDIM + d] = v.w;
        }
    }
    __syncthreads();

    unsigned qf[8][4];
#pragma unroll
    for (int kk = 0; kk < 8; kk++) {
        qf[kk][0] = f2tf(Qx[(q0 + lr)     * HDIM + kk * 8 + lc]);
        qf[kk][1] = f2tf(Qx[(q0 + 8 + lr) * HDIM + kk * 8 + lc]);
        qf[kk][2] = f2tf(Qx[(q0 + lr)     * HDIM + kk * 8 + lc + 4]);
        qf[kk][3] = f2tf(Qx[(q0 + 8 + lr) * HDIM + kk * 8 + lc + 4]);
    }

    float m0 = -1e30f, m1 = -1e30f, l0 = 0.0f, l1 = 0.0f;
    float O[8][4];
#pragma unroll
    for (int nt = 0; nt < 8; nt++)
#pragma unroll
        for (int i = 0; i < 4; i++) O[nt][i] = 0.0f;

    const int kvd = tid >> 2;
    const int kvs = (tid & 3) * 16;

    for (int t0 = 0; t0 < SEQ; t0 += KT) {
        __syncthreads();   // orders prior reads (incl. Qx/qf) before overwrite
#pragma unroll
        for (int j = 0; j < 16; j += 4) {
            const float4 kv = *(const float4*)&kg[(long)kvd * SEQ + t0 + kvs + j];
            const float4 vv = *(const float4*)&vg[(long)kvd * SEQ + t0 + kvs + j];
            unsigned* kp = &Ks[kvd * KS_STRIDE + kvs + j];
            kp[0] = f2tf(kv.x); kp[1] = f2tf(kv.y); kp[2] = f2tf(kv.z); kp[3] = f2tf(kv.w);
            Vt[(kvs + j)     * VT_STRIDE + kvd] = f2tf(vv.x);
            Vt[(kvs + j + 1) * VT_STRIDE + kvd] = f2tf(vv.y);
            Vt[(kvs + j + 2) * VT_STRIDE + kvd] = f2tf(vv.z);
            Vt[(kvs + j + 3) * VT_STRIDE + kvd] = f2tf(vv.w);
        }
        __syncthreads();

        float acc[8][4];
#pragma unroll
        for (int nt = 0; nt < 8; nt++)
#pragma unroll
            for (int i = 0; i < 4; i++) acc[nt][i] = 0.0f;

#pragma unroll
        for (int kk = 0; kk < 8; kk++) {
#pragma unroll
            for (int nt = 0; nt < 8; nt++) {
                const unsigned b0 = Ks[(kk * 8 + lc)     * KS_STRIDE + nt * 8 + lr];
                const unsigned b1 = Ks[(kk * 8 + lc + 4) * KS_STRIDE + nt * 8 + lr];
                mma_tf32(acc[nt], qf[kk][0], qf[kk][1], qf[kk][2], qf[kk][3], b0, b1);
            }
        }

        // Online softmax
        float rmax0 = -1e30f, rmax1 = -1e30f;
#pragma unroll
        for (int nt = 0; nt < 8; nt++) {
            rmax0 = fmaxf(rmax0, fmaxf(acc[nt][0], acc[nt][1]));
            rmax1 = fmaxf(rmax1, fmaxf(acc[nt][2], acc[nt][3]));
        }
        rmax0 *= SCALE; rmax1 *= SCALE;
#pragma unroll
        for (int off = 1; off <= 2; off <<= 1) {
            rmax0 = fmaxf(rmax0, __shfl_xor_sync(0xffffffffu, rmax0, off));
            rmax1 = fmaxf(rmax1, __shfl_xor_sync(0xffffffffu, rmax1, off));
        }
        const float mn0 = fmaxf(m0, rmax0), mn1 = fmaxf(m1, rmax1);
        const float al0 = __expf(m0 - mn0), al1 = __expf(m1 - mn1);
        m0 = mn0; m1 = mn1;

        float rs0 = 0.0f, rs1 = 0.0f;
#pragma unroll
        for (int nt = 0; nt < 8; nt++) {
            acc[nt][0] = __expf(acc[nt][0] * SCALE - m0); rs0 += acc[nt][0];
            acc[nt][1] = __expf(acc[nt][1] * SCALE - m0); rs0 += acc[nt][1];
            acc[nt][2] = __expf(acc[nt][2] * SCALE - m1); rs1 += acc[nt][2];
            acc[nt][3] = __expf(acc[nt][3] * SCALE - m1); rs1 += acc[nt][3];
        }
#pragma unroll
        for (int off = 1; off <= 2; off <<= 1) {
            rs0 += __shfl_xor_sync(0xffffffffu, rs0, off);
            rs1 += __shfl_xor_sync(0xffffffffu, rs1, off);
        }
        l0 = l0 * al0 + rs0;
        l1 = l1 * al1 + rs1;

#pragma unroll
        for (int nt = 0; nt < 8; nt++) {
            O[nt][0] *= al0; O[nt][1] *= al0;
            O[nt][2] *= al1; O[nt][3] *= al1;
        }

        // P.V : accum-layout -> A-fragment via quad shuffles
        const int sL1 = (lane & ~3) | (lc >> 1);
        const int sL2 = sL1 + 2;
        const bool odd = (lc & 1);
#pragma unroll
        for (int kc = 0; kc < 8; kc++) {
            const float q00 = __shfl_sync(0xffffffffu, acc[kc][0], sL1);
            const float q01 = __shfl_sync(0xffffffffu, acc[kc][1], sL1);
            const float q10 = __shfl_sync(0xffffffffu, acc[kc][2], sL1);
            const float q11 = __shfl_sync(0xffffffffu, acc[kc][3], sL1);
            const float r00 = __shfl_sync(0xffffffffu, acc[kc][0], sL2);
            const float r01 = __shfl_sync(0xffffffffu, acc[kc][1], sL2);
            const float r10 = __shfl_sync(0xffffffffu, acc[kc][2], sL2);
            const float r11 = __shfl_sync(0xffffffffu, acc[kc][3], sL2);
            const unsigned a0 = f2tf(odd ? q01 : q00);
            const unsigned a1 = f2tf(odd ? q11 : q10);
            const unsigned a2 = f2tf(odd ? r01 : r00);
            const unsigned a3 = f2tf(odd ? r11 : r10);
#pragma unroll
            for (int nt = 0; nt < 8; nt++) {
                const unsigned b0 = Vt[(kc * 8 + lc)     * VT_STRIDE + nt * 8 + lr];
                const unsigned b1 = Vt[(kc * 8 + lc + 4) * VT_STRIDE + nt * 8 + lr];
                mma_tf32(O[nt], a0, a1, a2, a3, b0, b1);
            }
        }
    }

    // Write out[b][h*64+d][s] = O / l
    float* og = out + (long)b * CC * SEQ + (long)(h * HDIM) * SEQ;
    const float inv0 = 1.0f / l0, inv1 = 1.0f / l1;
    const int s = s0 + q0 + lr;
#pragma unroll
    for (int nt = 0; nt < 8; nt++) {
        const int d0 = nt * 8 + 2 * lc;
        og[(long)d0 * SEQ + s]           = O[nt][0] * inv0;
        og[(long)(d0 + 1) * SEQ + s]     = O[nt][1] * inv0;
        og[(long)d0 * SEQ + s + 8]       = O[nt][2] * inv1;
        og[(long)(d0 + 1) * SEQ + s + 8] = O[nt][3] * inv1;
    }
}

// ---------------------------------------------------------------------------
extern "C" void kernel_launch(void* const* d_in, const int* in_sizes, int n_in,
                              void* d_out, int out_size)
{
    const float* x    = (const float*)d_in[0];
    const float* Wqkv = (const float*)d_in[1];
    const float* bqkv = (const float*)d_in[2];
    const float* Wout = (const float*)d_in[3];
    const float* bout = (const float*)d_in[4];
    float* out = (float*)d_out;

    float *qkvbuf = nullptr, *attbuf = nullptr;
    cudaGetSymbolAddress((void**)&qkvbuf, g_qkv);
    cudaGetSymbolAddress((void**)&attbuf, g_att);

    {
        dim3 grid(SEQ / G_BN, (3 * CC) / G_BM, BATCH);
        gemm_tf32_bias<<<grid, 256>>>(Wqkv, x, bqkv, qkvbuf,
                                      3 * CC, SEQ, CC,
                                      (long)CC * SEQ, (long)3 * CC * SEQ);
    }
    {
        dim3 grid(SEQ / QT, NHEADS, BATCH);
        attn_tf32<<<grid, 256>>>(qkvbuf, attbuf);
    }
    {
        dim3 grid(SEQ / G_BN, CC / G_BM, BATCH);
        gemm_tf32_bias<<<grid, 256>>>(Wout, attbuf, bout, out,
                                      CC, SEQ, CC,
                                      (long)CC * SEQ, (long)CC * SEQ);
    }
}